// round 6
// baseline (speedup 1.0000x reference)
#include <cuda_runtime.h>
#include <cuda_fp16.h>
#include <cstdint>

#define MTOT 4096
#define D_   768
#define H_   12
#define S_   2048

// ------------------------- scratch (__device__ globals) ---------------------
__device__ half g_xhi[MTOT * D_];
__device__ half g_xlo[MTOT * D_];
__device__ half g_wqkv_hi[3 * D_ * D_];   // [n=2304][k=768]  (W^T, hi)
__device__ half g_wqkv_lo[3 * D_ * D_];
__device__ half g_wo_hi[D_ * D_];
__device__ half g_wo_lo[D_ * D_];
__device__ half g_qkv[MTOT * 3 * D_];     // [token][2304]: q | k | v
__device__ half g_ctx[MTOT * D_];

// ------------------------- ptx helpers --------------------------------------
__device__ __forceinline__ uint32_t smem_u32(const void* p) {
    return (uint32_t)__cvta_generic_to_shared(p);
}
__device__ __forceinline__ void ldsm_x4(unsigned r[4], const void* p) {
    unsigned a = smem_u32(p);
    asm volatile("ldmatrix.sync.aligned.m8n8.x4.shared.b16 {%0,%1,%2,%3}, [%4];\n"
                 : "=r"(r[0]), "=r"(r[1]), "=r"(r[2]), "=r"(r[3]) : "r"(a));
}
__device__ __forceinline__ void ldsm_x4_t(unsigned r[4], const void* p) {
    unsigned a = smem_u32(p);
    asm volatile("ldmatrix.sync.aligned.m8n8.x4.trans.shared.b16 {%0,%1,%2,%3}, [%4];\n"
                 : "=r"(r[0]), "=r"(r[1]), "=r"(r[2]), "=r"(r[3]) : "r"(a));
}
__device__ __forceinline__ void mma16816(float c[4], const unsigned a[4], const unsigned b[2]) {
    asm volatile(
        "mma.sync.aligned.m16n8k16.row.col.f32.f16.f16.f32 "
        "{%0,%1,%2,%3}, {%4,%5,%6,%7}, {%8,%9}, {%0,%1,%2,%3};\n"
        : "+f"(c[0]), "+f"(c[1]), "+f"(c[2]), "+f"(c[3])
        : "r"(a[0]), "r"(a[1]), "r"(a[2]), "r"(a[3]), "r"(b[0]), "r"(b[1]));
}
__device__ __forceinline__ void cp_async16(uint32_t dst, const void* src) {
    asm volatile("cp.async.cg.shared.global [%0], [%1], 16;\n" :: "r"(dst), "l"(src));
}
__device__ __forceinline__ void cp_commit() {
    asm volatile("cp.async.commit_group;\n");
}
template<int N> __device__ __forceinline__ void cp_wait() {
    asm volatile("cp.async.wait_group %0;\n" :: "n"(N) : "memory");
}
__device__ __forceinline__ float ex2(float x) {
    float y;
    asm("ex2.approx.ftz.f32 %0, %1;" : "=f"(y) : "f"(x));
    return y;
}

// ------------------------- conversion kernels -------------------------------
__global__ void xsplit_kernel(const float* __restrict__ x,
                              half* __restrict__ hi, half* __restrict__ lo, int n4) {
    int i = blockIdx.x * 256 + threadIdx.x;
    if (i < n4) {
        float4 v = ((const float4*)x)[i];
        half h0 = __float2half_rn(v.x), h1 = __float2half_rn(v.y);
        half h2 = __float2half_rn(v.z), h3 = __float2half_rn(v.w);
        ((half2*)hi)[2 * i]     = __halves2half2(h0, h1);
        ((half2*)hi)[2 * i + 1] = __halves2half2(h2, h3);
        ((half2*)lo)[2 * i] = __halves2half2(
            __float2half_rn(v.x - __half2float(h0)), __float2half_rn(v.y - __half2float(h1)));
        ((half2*)lo)[2 * i + 1] = __halves2half2(
            __float2half_rn(v.z - __half2float(h2)), __float2half_rn(v.w - __half2float(h3)));
    }
}

// W [k][n] fp32 -> T [n][k] fp16 hi/lo. 4 matrices in one launch (z index).
__global__ void wsplit4_kernel(const float* __restrict__ W0, const float* __restrict__ W1,
                               const float* __restrict__ W2, const float* __restrict__ W3,
                               half* __restrict__ qh, half* __restrict__ ql,
                               half* __restrict__ oh, half* __restrict__ ol) {
    __shared__ float t[32][33];
    const int z = blockIdx.z;
    const float* W = (z == 0) ? W0 : (z == 1) ? W1 : (z == 2) ? W2 : W3;
    half* Thi = (z < 3) ? qh + (size_t)z * D_ * D_ : oh;
    half* Tlo = (z < 3) ? ql + (size_t)z * D_ * D_ : ol;
    const int bx = blockIdx.x * 32;  // k
    const int by = blockIdx.y * 32;  // n
    const int x = threadIdx.x, y = threadIdx.y;
#pragma unroll
    for (int i = y; i < 32; i += 8)
        t[i][x] = W[(size_t)(bx + i) * D_ + by + x];
    __syncthreads();
#pragma unroll
    for (int i = y; i < 32; i += 8) {
        float v = t[x][i];
        half hv = __float2half_rn(v);
        Thi[(size_t)(by + i) * D_ + bx + x] = hv;
        Tlo[(size_t)(by + i) * D_ + bx + x] = __float2half_rn(v - __half2float(hv));
    }
}

// ------------------------- split-fp16 GEMM (HMMA, big tiles) -----------------
// C[M=4096][N] = sum_{seg<nseg} A_seg[M][768] @ B_seg[N][768]^T + bias
// Block 256x128, Kt=64, 8 warps, warp tile 64x64, cp.async double buffer.
// Dynamic smem: stage = A 256x72 + B 128x72 halves = 55296 B; 2 stages = 110592 B.
#define GS_A_ROWS 256
#define GS_B_ROWS 128
#define GS_STRIDE 72
#define GS_STAGE  ((GS_A_ROWS + GS_B_ROWS) * GS_STRIDE)       // halves
#define GS_BOFF   (GS_A_ROWS * GS_STRIDE)                     // halves
#define GEMM_SMEM (2 * GS_STAGE * 2)                          // bytes = 110592

__global__ __launch_bounds__(256) void hgemm_big(
    const half* __restrict__ A0c, const half* __restrict__ A1c, const half* __restrict__ A2c,
    const half* __restrict__ B0c, const half* __restrict__ B1c, const half* __restrict__ B2c,
    const float* __restrict__ bias0, const float* __restrict__ bias1,
    const float* __restrict__ bias2,
    void* __restrict__ Cout, int N, int outIsHalf, int nseg)
{
    extern __shared__ __align__(16) half sm[];
    const int tid  = threadIdx.x;
    const int lane = tid & 31;
    const int w    = tid >> 5;
    const int wm   = (w >> 1) * 64;
    const int wn   = (w & 1) * 64;
    const int m0   = blockIdx.x * 256;
    const int n0   = blockIdx.y * 128;

    const half* Aseg[3] = {A0c, A1c, A2c};
    const half* Bseg[3] = {B0c, B1c, B2c};
    const int NIT = nseg * 12;   // k-chunks of 64

    // loader indices: A row = tid (0..255); B row = tid>>1, col half (tid&1)*32
    const int br = tid >> 1;
    const int bc = (tid & 1) * 32;

    auto prefetch = [&](int it, int s) {
        const int seg = it / 12;
        const int k0  = (it - seg * 12) * 64;
        const half* Ag = Aseg[seg] + (size_t)(m0 + tid) * D_ + k0;
        const half* Bg = Bseg[seg] + (size_t)(n0 + br) * D_ + k0 + bc;
        uint32_t ad = smem_u32(sm + s * GS_STAGE + tid * GS_STRIDE);
#pragma unroll
        for (int i = 0; i < 8; ++i) cp_async16(ad + i * 16, Ag + i * 8);
        uint32_t bd = smem_u32(sm + s * GS_STAGE + GS_BOFF + br * GS_STRIDE + bc);
#pragma unroll
        for (int i = 0; i < 4; ++i) cp_async16(bd + i * 16, Bg + i * 8);
        cp_commit();
    };

    float c[4][8][4];
#pragma unroll
    for (int i = 0; i < 4; i++)
#pragma unroll
        for (int j = 0; j < 8; j++)
#pragma unroll
            for (int k = 0; k < 4; k++) c[i][j][k] = 0.f;

    prefetch(0, 0);
    prefetch(1, 1);

    for (int it = 0; it < NIT; ++it) {
        const int cb = it & 1;
        if (it < NIT - 1) cp_wait<1>(); else cp_wait<0>();
        __syncthreads();

        const half* Abase = sm + cb * GS_STAGE;
        const half* Bbase = sm + cb * GS_STAGE + GS_BOFF;
#pragma unroll
        for (int kk = 0; kk < 4; ++kk) {
            unsigned a[4][4];
            unsigned b[8][2];
#pragma unroll
            for (int mf = 0; mf < 4; ++mf)
                ldsm_x4(a[mf], Abase + (wm + mf * 16 + (lane & 15)) * GS_STRIDE
                                     + kk * 16 + (lane >> 4) * 8);
#pragma unroll
            for (int bg = 0; bg < 4; ++bg) {
                unsigned r[4];
                ldsm_x4(r, Bbase + (wn + bg * 16 + ((lane & 7) | ((lane >> 4) << 3))) * GS_STRIDE
                                 + kk * 16 + ((lane >> 3) & 1) * 8);
                b[2 * bg][0] = r[0]; b[2 * bg][1] = r[1];
                b[2 * bg + 1][0] = r[2]; b[2 * bg + 1][1] = r[3];
            }
#pragma unroll
            for (int mf = 0; mf < 4; ++mf)
#pragma unroll
                for (int nf = 0; nf < 8; ++nf)
                    mma16816(c[mf][nf], a[mf], b[nf]);
        }
        __syncthreads();
        if (it + 2 < NIT) prefetch(it + 2, cb);
    }

    // epilogue: bias (column-segmented) + store
#pragma unroll
    for (int mf = 0; mf < 4; ++mf) {
#pragma unroll
        for (int nf = 0; nf < 8; ++nf) {
            const int row = m0 + wm + mf * 16 + (lane >> 2);
            const int col = n0 + wn + nf * 8 + 2 * (lane & 3);
            float bb0 = col < 768 ? bias0[col] : (col < 1536 ? bias1[col - 768] : bias2[col - 1536]);
            int c1i = col + 1;
            float bb1 = c1i < 768 ? bias0[c1i] : (c1i < 1536 ? bias1[c1i - 768] : bias2[c1i - 1536]);
            float v0 = c[mf][nf][0] + bb0, v1 = c[mf][nf][1] + bb1;
            float v2 = c[mf][nf][2] + bb0, v3 = c[mf][nf][3] + bb1;
            if (outIsHalf) {
                half* C = (half*)Cout;
                *(half2*)&C[(size_t)row * N + col]       = __floats2half2_rn(v0, v1);
                *(half2*)&C[(size_t)(row + 8) * N + col] = __floats2half2_rn(v2, v3);
            } else {
                float* C = (float*)Cout;
                *(float2*)&C[(size_t)row * N + col]       = make_float2(v0, v1);
                *(float2*)&C[(size_t)(row + 8) * N + col] = make_float2(v2, v3);
            }
        }
    }
}

// ------------------------- flash attention on HMMA (cp.async) ---------------
__global__ __launch_bounds__(256) void attn_mma(
    const half* __restrict__ qkv, half* __restrict__ ctx)
{
    __shared__ __align__(16) half KV[2][2][64][72];
    half (*Qs)[72] = reinterpret_cast<half(*)[72]>(&KV[0][0][0][0]);  // 128x72

    const int tid  = threadIdx.x;
    const int lane = tid & 31;
    const int w    = tid >> 5;
    const int qt = blockIdx.x, h = blockIdx.y, b = blockIdx.z;
    const int tok0 = b * S_ + qt * 128;
    const int hoff = h * 64;

    {
        const int lr = tid >> 1;
        const int lc = (tid & 1) * 32;
        const half2 s2 = __half2half2(__float2half(0.125f * 1.4426950408889634f));
#pragma unroll
        for (int i = 0; i < 4; i++) {
            int kc = lc + i * 8;
            float4 v = *(const float4*)&qkv[(size_t)(tok0 + lr) * 2304 + hoff + kc];
            half2* hp = (half2*)&v;
#pragma unroll
            for (int q = 0; q < 4; q++) hp[q] = __hmul2(hp[q], s2);
            *(float4*)&Qs[lr][kc] = v;
        }
    }
    __syncthreads();
    unsigned qa[4][4];
#pragma unroll
    for (int kk = 0; kk < 4; kk++)
        ldsm_x4(qa[kk], &Qs[w * 16 + (lane & 15)][kk * 16 + (lane >> 4) * 8]);
    __syncthreads();

    const int pr = tid >> 2;
    const int pc = (tid & 3) * 16;
    auto prefetch = [&](int kt, int buf) {
        const int kt0 = b * S_ + kt * 64;
        const half* kp = &qkv[(size_t)(kt0 + pr) * 2304 + 768 + hoff + pc];
        uint32_t kd = smem_u32(&KV[buf][0][pr][pc]);
        uint32_t vd = smem_u32(&KV[buf][1][pr][pc]);
        cp_async16(kd, kp);       cp_async16(kd + 16, kp + 8);
        cp_async16(vd, kp + 768); cp_async16(vd + 16, kp + 776);
        cp_commit();
    };

    float acc[8][4];
#pragma unroll
    for (int i = 0; i < 8; i++)
#pragma unroll
        for (int j = 0; j < 4; j++) acc[i][j] = 0.f;
    float mlo = -1e30f, mhi = -1e30f, llo = 0.f, lhi = 0.f;

    prefetch(0, 0);
    prefetch(1, 1);

    const int NT = S_ / 64;
    for (int kt = 0; kt < NT; kt++) {
        const int cb = kt & 1;
        if (kt < NT - 1) cp_wait<1>(); else cp_wait<0>();
        __syncthreads();
        half (*Ks)[72] = KV[cb][0];
        half (*Vs)[72] = KV[cb][1];

        float sc[8][4];
#pragma unroll
        for (int i = 0; i < 8; i++)
#pragma unroll
            for (int j = 0; j < 4; j++) sc[i][j] = 0.f;
#pragma unroll
        for (int kk = 0; kk < 4; kk++) {
#pragma unroll
            for (int g = 0; g < 4; g++) {
                unsigned r[4];
                ldsm_x4(r, &Ks[g * 16 + ((lane & 7) | ((lane >> 4) << 3))]
                              [kk * 16 + ((lane >> 3) & 1) * 8]);
                unsigned b0[2] = {r[0], r[1]}, b1[2] = {r[2], r[3]};
                mma16816(sc[2 * g],     qa[kk], b0);
                mma16816(sc[2 * g + 1], qa[kk], b1);
            }
        }

        float tlo = -1e30f, thi = -1e30f;
#pragma unroll
        for (int nf = 0; nf < 8; nf++) {
            tlo = fmaxf(tlo, fmaxf(sc[nf][0], sc[nf][1]));
            thi = fmaxf(thi, fmaxf(sc[nf][2], sc[nf][3]));
        }
        tlo = fmaxf(tlo, __shfl_xor_sync(0xffffffffu, tlo, 1));
        tlo = fmaxf(tlo, __shfl_xor_sync(0xffffffffu, tlo, 2));
        thi = fmaxf(thi, __shfl_xor_sync(0xffffffffu, thi, 1));
        thi = fmaxf(thi, __shfl_xor_sync(0xffffffffu, thi, 2));
        float m2lo = fmaxf(mlo, tlo), m2hi = fmaxf(mhi, thi);
        float clo = ex2(mlo - m2lo), chi = ex2(mhi - m2hi);
        mlo = m2lo; mhi = m2hi;

        unsigned pa[4][4];
        float slo = 0.f, shi = 0.f;
#pragma unroll
        for (int j = 0; j < 4; j++) {
#pragma unroll
            for (int t = 0; t < 2; t++) {
                const int nf = 2 * j + t;
                float p0 = ex2(sc[nf][0] - m2lo);
                float p1 = ex2(sc[nf][1] - m2lo);
                float p2 = ex2(sc[nf][2] - m2hi);
                float p3 = ex2(sc[nf][3] - m2hi);
                slo += p0 + p1; shi += p2 + p3;
                half2 hl = __floats2half2_rn(p0, p1);
                half2 hh = __floats2half2_rn(p2, p3);
                pa[j][2 * t]     = *reinterpret_cast<unsigned*>(&hl);
                pa[j][2 * t + 1] = *reinterpret_cast<unsigned*>(&hh);
            }
        }
        slo += __shfl_xor_sync(0xffffffffu, slo, 1);
        slo += __shfl_xor_sync(0xffffffffu, slo, 2);
        shi += __shfl_xor_sync(0xffffffffu, shi, 1);
        shi += __shfl_xor_sync(0xffffffffu, shi, 2);
        llo = llo * clo + slo;
        lhi = lhi * chi + shi;
#pragma unroll
        for (int nf = 0; nf < 8; nf++) {
            acc[nf][0] *= clo; acc[nf][1] *= clo;
            acc[nf][2] *= chi; acc[nf][3] *= chi;
        }

#pragma unroll
        for (int j = 0; j < 4; j++) {
#pragma unroll
            for (int g = 0; g < 4; g++) {
                unsigned r[4];
                ldsm_x4_t(r, &Vs[j * 16 + (lane & 15)][g * 16 + (lane >> 4) * 8]);
                unsigned b0[2] = {r[0], r[1]}, b1[2] = {r[2], r[3]};
                mma16816(acc[2 * g],     pa[j], b0);
                mma16816(acc[2 * g + 1], pa[j], b1);
            }
        }
        __syncthreads();
        if (kt + 2 < NT) prefetch(kt + 2, cb);
    }

    const float ilo = 1.f / llo, ihi = 1.f / lhi;
    const int row = tok0 + w * 16 + (lane >> 2);
#pragma unroll
    for (int nf = 0; nf < 8; nf++) {
        const int col = hoff + nf * 8 + 2 * (lane & 3);
        *(half2*)&ctx[(size_t)row * D_ + col] =
            __floats2half2_rn(acc[nf][0] * ilo, acc[nf][1] * ilo);
        *(half2*)&ctx[(size_t)(row + 8) * D_ + col] =
            __floats2half2_rn(acc[nf][2] * ihi, acc[nf][3] * ihi);
    }
}

// ------------------------- launch -------------------------------------------
extern "C" void kernel_launch(void* const* d_in, const int* in_sizes, int n_in,
                              void* d_out, int out_size)
{
    (void)in_sizes; (void)n_in; (void)out_size;
    const float* x  = (const float*)d_in[0];
    const float* Wq = (const float*)d_in[1];
    const float* bq = (const float*)d_in[2];
    const float* Wk = (const float*)d_in[3];
    const float* bk = (const float*)d_in[4];
    const float* Wv = (const float*)d_in[5];
    const float* bv = (const float*)d_in[6];
    const float* Wo = (const float*)d_in[7];
    const float* bo = (const float*)d_in[8];
    float* out = (float*)d_out;

    half *xhi, *xlo, *wqh, *wql, *woh, *wol, *qkv, *ctx;
    cudaGetSymbolAddress((void**)&xhi, g_xhi);
    cudaGetSymbolAddress((void**)&xlo, g_xlo);
    cudaGetSymbolAddress((void**)&wqh, g_wqkv_hi);
    cudaGetSymbolAddress((void**)&wql, g_wqkv_lo);
    cudaGetSymbolAddress((void**)&woh, g_wo_hi);
    cudaGetSymbolAddress((void**)&wol, g_wo_lo);
    cudaGetSymbolAddress((void**)&qkv, g_qkv);
    cudaGetSymbolAddress((void**)&ctx, g_ctx);

    cudaFuncSetAttribute(hgemm_big, cudaFuncAttributeMaxDynamicSharedMemorySize, GEMM_SMEM);

    const int N4 = MTOT * D_ / 4;
    xsplit_kernel<<<(N4 + 255) / 256, 256>>>(x, xhi, xlo, N4);
    wsplit4_kernel<<<dim3(24, 24, 4), dim3(32, 8)>>>(Wq, Wk, Wv, Wo, wqh, wql, woh, wol);

    // QKV projection: xhi@Whi^T + xlo@Whi^T + xhi@Wlo^T  (3 segments)
    hgemm_big<<<dim3(16, 18), 256, GEMM_SMEM>>>(xhi, xlo, xhi,
                                                wqh, wqh, wql,
                                                bq, bk, bv,
                                                qkv, 2304, 1, 3);

    attn_mma<<<dim3(S_ / 128, H_, 2), 256>>>(qkv, ctx);

    // output projection (fp32 out): ctx@Woh^T + ctx@Wol^T  (2 segments)
    hgemm_big<<<dim3(16, 6), 256, GEMM_SMEM>>>(ctx, ctx, ctx,
                                               woh, wol, wol,
                                               bo, bo, bo,
                                               out, 768, 0, 2);
}